// round 15
// baseline (speedup 1.0000x reference)
#include <cuda_runtime.h>
#include <cuda_bf16.h>
#include <mma.h>
#include <cstdint>

using namespace nvcuda;

// Problem constants
#define Bq 32
#define Sq 2048
#define Dq 512
#define Hq 32
#define NTOK (Bq * Sq)        // 65536
#define GRID 152
#define NT   512              // 16 warps = 4 independent streams of 4

// ---------------- shared layout (float offsets) ----------------
#define XB_STRIDE 520             // bf16 row stride (1040B)
#define F_STRIDE  520             // fp32 row stride (2080B -> 32B rotation)
#define WS_STRIDE 40
#define SM_HT   0                 // Ht[32][36] plain                 -> 1152
#define SM_TBL  1152              // ints P[33]+scnt[32], pad         -> 1232
#define SM_SW   1232              // per-stream ints [8]              -> 1240 (pad 1248)
#define SM_WS   1248              // Ws[4][8][40]                     -> 2528
#define SM_XB   2528              // Xb bf16 [4][8][520]  (8320 f)    -> 10848
#define SM_F    10848             // F fp32 [4][2][8][520] (33280 f)  -> 44128
#define SM_PB   44128             // P bf16 [32][520] (8320 f)        -> 52448
#define SM_FLOATS 52448
#define SMEM_BYTES (SM_FLOATS * 4)   // 209792

#define RSCALE 0.17677669529663687f  // 1/sqrt(32)

// ---------------- scratch ----------------
__device__ int      g_bcnt[256];
__device__ int      g_cnt[Bq];
__device__ int      g_idx[NTOK];
__device__ float    g_bsum[Bq];
__device__ float    g_acc[Bq * Dq];
__device__ unsigned g_bar1 = 0u;
__device__ unsigned g_bar2 = 0u;
__device__ unsigned g_work = 0u;     // dynamic slice counter (reset by k_prep)

// ---------------- helpers ----------------
__device__ __forceinline__ void fma2(unsigned long long& d,
                                     unsigned long long a,
                                     unsigned long long b) {
    asm("fma.rn.f32x2 %0, %1, %2, %3;" : "=l"(d) : "l"(a), "l"(b), "l"(d));
}
__device__ __forceinline__ float2 upk(unsigned long long v) {
    float2 r;
    asm("mov.b64 {%0, %1}, %2;" : "=f"(r.x), "=f"(r.y) : "l"(v));
    return r;
}
__device__ __forceinline__ float sigmoidf(float v) {
    return 1.0f / (1.0f + __expf(-v));
}
__device__ __forceinline__ void stream_bar(int id) {
    asm volatile("bar.sync %0, 128;" :: "r"(id) : "memory");
}
__device__ __forceinline__ unsigned pack_bf2(float a, float b) {
    __nv_bfloat162 t = __float22bfloat162_rn(make_float2(a, b));
    return *(unsigned*)&t;
}
__device__ __forceinline__ uint32_t smem_u32(const void* p) {
    uint32_t a;
    asm("{ .reg .u64 t; cvta.to.shared.u64 t, %1; cvt.u32.u64 %0, t; }"
        : "=r"(a) : "l"(p));
    return a;
}
__device__ __forceinline__ void cp16(uint32_t dst, const void* src) {
    asm volatile("cp.async.cg.shared.global [%0], [%1], 16;"
                 :: "r"(dst), "l"(src) : "memory");
}
#define CP_COMMIT() asm volatile("cp.async.commit_group;" ::: "memory")
#define CP_WAIT0()  asm volatile("cp.async.wait_group 0;" ::: "memory")

__device__ __forceinline__ bool mask_on(const void* mask, int mm, int t) {
    if (mm == 1) return ((const int*)mask)[t] != 0;
    if (mm == 2) return ((const float*)mask)[t] != 0.0f;
    return ((const unsigned char*)mask)[t] != 0;
}
__device__ __forceinline__ int detect_mode(const unsigned int* m, int lane) {
    bool ai = true, af = true;
#pragma unroll
    for (int k = 0; k < 8; ++k) {
        unsigned v = m[lane * 8 + k];
        ai &= (v <= 1u);
        af &= (v == 0u || v == 0x3F800000u);
    }
    unsigned bi = __ballot_sync(0xffffffffu, ai);
    unsigned bf = __ballot_sync(0xffffffffu, af);
    return (bi == 0xffffffffu) ? 1 : ((bf == 0xffffffffu) ? 2 : 0);
}

// Monotonic grid barrier (all nb blocks co-resident; counter never resets).
__device__ __forceinline__ void grid_barrier(unsigned* bar, unsigned nb) {
    __syncthreads();
    if (threadIdx.x == 0) {
        __threadfence();
        unsigned r = atomicAdd(bar, 1u);
        unsigned target = (r / nb + 1u) * nb;
        while (*((volatile unsigned*)bar) < target) {}
    }
    __syncthreads();
}

// -------------------- kernel 1: one-pass ordered per-batch compaction ------
__global__ void k_prep(const void* mask) {
    __shared__ int wcnt[8];
    __shared__ int s_mode;
    const int tid = threadIdx.x, bid = blockIdx.x;
    const int lane = tid & 31, wid = tid >> 5;

    if (bid == 0 && tid == 0) g_work = 0u;   // reset dynamic scheduler
    if (wid == 0) {
        int md = detect_mode((const unsigned int*)mask, lane);
        if (lane == 0) s_mode = md;
    }
    const int g = bid * 256 + tid;
    if (bid < 64) g_acc[g] = 0.0f;
    if (g < Bq) g_bsum[g] = 0.0f;
    __syncthreads();

    const bool on = mask_on(mask, s_mode, g);
    const unsigned bal = __ballot_sync(0xffffffffu, on);
    if (lane == 0) wcnt[wid] = __popc(bal);
    __syncthreads();

    int btot = 0, wbase = 0;
#pragma unroll
    for (int w = 0; w < 8; ++w) {
        if (w < wid) wbase += wcnt[w];
        btot += wcnt[w];
    }
    if (tid == 0) g_bcnt[bid] = btot;

    grid_barrier(&g_bar1, 256);

    const int b = bid >> 3;
    int off = 0, cnt = 0;
#pragma unroll
    for (int j = 0; j < 8; ++j) {
        int idx = b * 8 + j;
        int v = __ldcg(&g_bcnt[idx]);
        cnt += v;
        if (idx < bid) off += v;
    }
    if (tid == 0) g_cnt[b] = cnt;
    if (on)
        g_idx[b * 2048 + off + wbase + __popc(bal & ((1u << lane) - 1u))] = g;
}

// -------------------- kernel 2: persistent main + fused final --------------
// 512 threads = 4 independent 4-warp streams; 8-token slices. X staged by
// cp.async into double-buffered fp32 smem; bf16 conversion and epilogue read
// smem only.
__global__ void __launch_bounds__(NT) k_main(const float* __restrict__ inp,
                                             const float* __restrict__ proj,
                                             const float* __restrict__ hid,
                                             const float* __restrict__ ev,
                                             float* __restrict__ out) {
    extern __shared__ float sm[];
    const int tid    = threadIdx.x;
    const int lane   = tid & 31;
    const int wid    = tid >> 5;
    const int stream = wid >> 2;     // 0..3
    const int hw     = wid & 2 ? (wid & 3) : (wid & 3);  // warp within stream
    const int hw4    = wid & 3;
    const int t128   = tid & 127;
    const int barid  = 1 + stream;   // named barriers 1..4
    const int r_own  = t128 >> 4;    // owned row (0..7) for cp.async/convert
    const int lane16 = t128 & 15;

    float*          Fs = sm + SM_F + stream * (2 * 8 * F_STRIDE);
    __nv_bfloat16*  Xb = (__nv_bfloat16*)(sm + SM_XB) + stream * (8 * XB_STRIDE);
    __nv_bfloat16*  Pb = (__nv_bfloat16*)(sm + SM_PB);
    float*          Ws = sm + SM_WS + stream * (8 * WS_STRIDE);
    volatile int*   sW = (volatile int*)(sm + SM_SW);

    // ---- stage P as bf16: Pb[n][k] = proj[k*32+n] ----
    for (int i = tid; i < Dq * Hq; i += NT) {
        int k = i >> 5, n = i & 31;
        Pb[n * XB_STRIDE + k] = __float2bfloat16(proj[i]);
    }
    // ---- stage Ht plain stride 36: Ht[k][h] = hid[h*32+k] ----
    for (int i = tid; i < Hq * Hq; i += NT) {
        int k = i >> 5, h = i & 31;
        sm[SM_HT + k * 36 + h] = hid[h * Hq + k];
    }
    const int   tp  = lane >> 4;       // token within warp pair (0/1)
    const int   hl  = lane & 15;       // h-pair index
    const float2 ev2 = ((const float2*)ev)[hl];

    // ---- slice table: inclusive prefix of per-batch 8-token slice counts --
    int* P    = (int*)(sm + SM_TBL);
    int* scnt = (int*)(sm + SM_TBL) + 33;
    if (tid < 32) {
        int c = g_cnt[tid];
        scnt[tid] = c;
        int x = (c + 7) >> 3;
#pragma unroll
        for (int o = 1; o < 32; o <<= 1) {
            int y = __shfl_up_sync(0xffffffffu, x, o);
            if (lane >= o) x += y;
        }
        P[tid + 1] = x;
        if (tid == 0) P[0] = 0;
    }
    // ---- prologue work grabs: 2 slice ids per stream ----
    if (t128 == 0) {
        sW[stream * 2 + 0] = (int)atomicAdd(&g_work, 1u);
        sW[stream * 2 + 1] = (int)atomicAdd(&g_work, 1u);
    }
    __syncthreads();
    const int NS = P[32];

    int s_cur  = sW[stream * 2 + 0];
    int s_next = sW[stream * 2 + 1];
    int p = 0;

    // slice -> (batch, local slice, count)
    auto slice_info = [&](int s, int& b, int& sl, int& cnt) {
        int bb = 0;
        while (s >= P[bb + 1]) ++bb;
        b = bb; sl = s - P[bb]; cnt = scnt[bb];
    };
    // issue cp.async for a slice into buffer Fdst (all 128 threads share rows)
    auto issue_stage = [&](int s, float* Fdst) {
        int b, sl, cnt;
        slice_info(s, b, sl, cnt);
        int jr  = sl * 8 + r_own;
        int tok = g_idx[b * 2048 + min(jr, cnt - 1)];
        const char* src = (const char*)(inp + (size_t)tok * Dq) + lane16 * 16;
        uint32_t dst = smem_u32(Fdst) + (uint32_t)r_own * (F_STRIDE * 4) +
                       (uint32_t)lane16 * 16u;
#pragma unroll
        for (int j = 0; j < 8; ++j)
            cp16(dst + j * 256u, src + j * 256);
    };

    if (s_cur < NS) issue_stage(s_cur, Fs);
    CP_COMMIT();

    const float* HtA = sm + SM_HT + (2 * hl) * 36;
    const float* HtB = HtA + 36;

    while (s_cur < NS) {
        float* Fp = Fs + p * (8 * F_STRIDE);
        int b, sl, cnt;
        slice_info(s_cur, b, sl, cnt);

        // ---- wait own cp.async chunks; sync stream ----
        CP_WAIT0();
        stream_bar(barid);              // all rows landed; Xb free to rewrite

        // ---- convert own row chunks F[p] -> Xb (same chunks as cp.async) ----
        {
            const float* Fr = Fp + r_own * F_STRIDE;
            __nv_bfloat16* Xr = Xb + r_own * XB_STRIDE;
#pragma unroll
            for (int j = 0; j < 8; ++j) {
                int c = (lane16 + j * 16) * 4;
                float4 v = *(const float4*)(Fr + c);
                uint2 pk;
                pk.x = pack_bf2(v.x, v.y);
                pk.y = pack_bf2(v.z, v.w);
                *(uint2*)((char*)Xr + c * 2) = pk;
            }
        }
        if (t128 == 0) sW[stream * 2] = (int)atomicAdd(&g_work, 1u);
        stream_bar(barid);              // Xb ready; next work id visible
        const int s_next2 = sW[stream * 2];

        // ---- prefetch next slice into other buffer (fully async) ----
        if (s_next < NS) issue_stage(s_next, Fs + (p ^ 1) * (8 * F_STRIDE));
        CP_COMMIT();

        // ---- projector GEMM: warp 0 -> Z[8 tok x 32 h] (m8n32k16) ----
        if (hw4 == 0) {
            wmma::fragment<wmma::accumulator, 8, 32, 16, float> c;
            wmma::fill_fragment(c, 0.0f);
#pragma unroll 4
            for (int ks = 0; ks < 32; ++ks) {
                wmma::fragment<wmma::matrix_a, 8, 32, 16, __nv_bfloat16,
                               wmma::row_major> a;
                wmma::fragment<wmma::matrix_b, 8, 32, 16, __nv_bfloat16,
                               wmma::col_major> bf;
                wmma::load_matrix_sync(a, Xb + ks * 16, XB_STRIDE);
                wmma::load_matrix_sync(bf, Pb + ks * 16, XB_STRIDE);
                wmma::mma_sync(c, a, bf, c);
            }
#pragma unroll
            for (int t = 0; t < c.num_elements; ++t)
                c.x[t] = sigmoidf(c.x[t] * RSCALE);
            wmma::store_matrix_sync(Ws, c, WS_STRIDE, wmma::mem_row_major);
        }
        stream_bar(barid);              // Ws ready

        // ---- hidden + evaluator: 2 tokens per warp (proven R9 variant) ----
        {
            const int trow = hw4 * 2 + tp;
            const float* w0r = Ws + trow * WS_STRIDE;
            unsigned long long a0 = 0ull, a1 = 0ull;
#pragma unroll
            for (int c = 0; c < 8; ++c) {
                ulonglong2 wv = *(const ulonglong2*)(w0r + (c << 2));
                ulonglong2 q0 = *(const ulonglong2*)(HtA + (c << 2));
                ulonglong2 q1 = *(const ulonglong2*)(HtB + (c << 2));
                fma2(a0, wv.x, q0.x); fma2(a0, wv.y, q0.y);
                fma2(a1, wv.x, q1.x); fma2(a1, wv.y, q1.y);
            }
            float2 r0 = upk(a0), r1 = upk(a1);
            float e = sigmoidf((r0.x + r0.y) * RSCALE) * ev2.x +
                      sigmoidf((r1.x + r1.y) * RSCALE) * ev2.y;
            e += __shfl_xor_sync(0xffffffffu, e, 1);
            e += __shfl_xor_sync(0xffffffffu, e, 2);
            e += __shfl_xor_sync(0xffffffffu, e, 4);
            e += __shfl_xor_sync(0xffffffffu, e, 8);
            float z = sigmoidf(e * RSCALE);
            bool valid = (sl * 8 + trow) < cnt;
            float wf = valid ? __expf(z) : 0.0f;
            if (hl == 0) Ws[trow * WS_STRIDE + 32] = wf;
            // warp's 2-token weight sum -> g_bsum
            float ww = (hl == 0) ? wf : 0.0f;
            ww += __shfl_xor_sync(0xffffffffu, ww, 16);
            if (lane == 0) atomicAdd(&g_bsum[b], ww);
        }
        stream_bar(barid);              // all 8 wf visible

        // ---- epilogue: warp covers d-quarter over 8 tokens, fp32 from smem -
        {
            float4 acc = make_float4(0.f, 0.f, 0.f, 0.f);
            const float* Fd = Fp + hw4 * 128 + lane * 4;
#pragma unroll
            for (int tt = 0; tt < 8; ++tt) {
                float wf = Ws[tt * WS_STRIDE + 32];
                float4 v = *(const float4*)(Fd + tt * F_STRIDE);
                acc.x += wf * v.x;
                acc.y += wf * v.y;
                acc.z += wf * v.z;
                acc.w += wf * v.w;
            }
            float* dst = g_acc + b * Dq + hw4 * 128 + lane * 4;
            atomicAdd(dst + 0, acc.x);
            atomicAdd(dst + 1, acc.y);
            atomicAdd(dst + 2, acc.z);
            atomicAdd(dst + 3, acc.w);
        }

        s_cur = s_next;
        s_next = s_next2;
        p ^= 1;
    }

    // ---- fused final: grid barrier, then normalize ----
    grid_barrier(&g_bar2, GRID);
    const int g = blockIdx.x * NT + tid;
    if (g < Bq * Dq)
        out[g] = __ldcg(&g_acc[g]) / (__ldcg(&g_bsum[g >> 9]) + 1e-12f);
}

// -------------------- launcher --------------------
extern "C" void kernel_launch(void* const* d_in, const int* in_sizes, int n_in,
                              void* d_out, int out_size) {
    const float* inp  = (const float*)d_in[0];
    const void*  mask = d_in[1];
    const float* proj = (const float*)d_in[2];
    const float* hid  = (const float*)d_in[3];
    const float* ev   = (const float*)d_in[4];
    float* out = (float*)d_out;

    cudaFuncSetAttribute(k_main, cudaFuncAttributeMaxDynamicSharedMemorySize,
                         SMEM_BYTES);

    k_prep<<<256, 256>>>(mask);
    k_main<<<GRID, NT, SMEM_BYTES>>>(inp, proj, hid, ev, out);
}